// round 13
// baseline (speedup 1.0000x reference)
#include <cuda_runtime.h>
#include <cuda_bf16.h>
#include <cstdint>

#define BB 4
#define HH 8
#define LQ 512
#define NBLK 32
#define NTOK 128
#define DH 64
#define MT 128
#define THREADS 256

#define OUT_ELEMS  (BB * LQ * HH * DH)
#define ATTN_ELEMS ((size_t)BB * HH * LQ * NBLK * NTOK)

#define QSTR 72          // bf16 elements per row (64 + 8 pad)
#define RB (QSTR * 2)    // 144 bytes per row
#define TILE (128 * RB)  // 18432 bytes per 128-row tile
#define TBUF (4 * TILE)  // KH,KL,VH,VL

// smem byte offsets
#define OFF_QH 0
#define OFF_QL (OFF_QH + TILE)
#define OFF_T0 (OFF_QL + TILE)          // buffer 0: KH,KL,VH,VL
#define OFF_T1 (OFF_T0 + TBUF)          // buffer 1
#define OFF_RS (OFF_T1 + TBUF)          // 128*2 f32 rowsums
#define OFF_STG (OFF_RS + 1024)         // 32KB raw stage (K then V ping)
#define SMEM_BYTES (OFF_STG + 32768)    // 218112

#define RED_STR 66

typedef unsigned long long ull;

__device__ __forceinline__ uint32_t s2u(const void* p) {
    uint32_t a;
    asm("{ .reg .u64 t; cvta.to.shared.u64 t, %1; cvt.u32.u64 %0, t; }" : "=r"(a) : "l"(p));
    return a;
}
__device__ __forceinline__ ull pack2(float x, float y) {
    ull r; asm("mov.b64 %0, {%1,%2};" : "=l"(r) : "f"(x), "f"(y)); return r;
}
__device__ __forceinline__ void unpack2(ull v, float& x, float& y) {
    asm("mov.b64 {%0,%1}, %2;" : "=f"(x), "=f"(y) : "l"(v));
}
__device__ __forceinline__ ull add2(ull a, ull b) {
    ull d; asm("add.rn.f32x2 %0, %1, %2;" : "=l"(d) : "l"(a), "l"(b)); return d;
}
__device__ __forceinline__ ull mul2(ull a, ull b) {
    ull d; asm("mul.rn.f32x2 %0, %1, %2;" : "=l"(d) : "l"(a), "l"(b)); return d;
}
__device__ __forceinline__ ull fma2(ull a, ull b, ull c) {
    ull d; asm("fma.rn.f32x2 %0, %1, %2, %3;" : "=l"(d) : "l"(a), "l"(b), "l"(c)); return d;
}
__device__ __forceinline__ void ldsm4(uint32_t* r, uint32_t a) {
    asm volatile("ldmatrix.sync.aligned.m8n8.x4.shared.b16 {%0,%1,%2,%3}, [%4];"
                 : "=r"(r[0]), "=r"(r[1]), "=r"(r[2]), "=r"(r[3]) : "r"(a));
}
__device__ __forceinline__ void ldsm4t(uint32_t* r, uint32_t a) {
    asm volatile("ldmatrix.sync.aligned.m8n8.x4.trans.shared.b16 {%0,%1,%2,%3}, [%4];"
                 : "=r"(r[0]), "=r"(r[1]), "=r"(r[2]), "=r"(r[3]) : "r"(a));
}
__device__ __forceinline__ void mma16816(float* c, const uint32_t* a, const uint32_t* b) {
    asm volatile(
        "mma.sync.aligned.m16n8k16.row.col.f32.bf16.bf16.f32 "
        "{%0,%1,%2,%3}, {%4,%5,%6,%7}, {%8,%9}, {%0,%1,%2,%3};"
        : "+f"(c[0]), "+f"(c[1]), "+f"(c[2]), "+f"(c[3])
        : "r"(a[0]), "r"(a[1]), "r"(a[2]), "r"(a[3]), "r"(b[0]), "r"(b[1]));
}
__device__ __forceinline__ void cpa16(uint32_t dst, const void* src) {
    asm volatile("cp.async.cg.shared.global [%0], [%1], 16;" :: "r"(dst), "l"(src));
}
#define CP_COMMIT() asm volatile("cp.async.commit_group;" ::: "memory")
#define CP_WAIT0()  asm volatile("cp.async.wait_group 0;" ::: "memory")
__device__ __forceinline__ void barpair(int id) {
    asm volatile("bar.sync %0, 64;" :: "r"(id) : "memory");
}

// split one fp32 float4 into bf16 hi/lo, store 8B each
__device__ __forceinline__ void split_store(float4 v, char* base_hi, char* base_lo) {
    __nv_bfloat162 h0 = __floats2bfloat162_rn(v.x, v.y);
    __nv_bfloat162 h1 = __floats2bfloat162_rn(v.z, v.w);
    float lx = v.x - __bfloat162float(h0.x);
    float ly = v.y - __bfloat162float(h0.y);
    float lz = v.z - __bfloat162float(h1.x);
    float lw = v.w - __bfloat162float(h1.y);
    __nv_bfloat162 e0 = __floats2bfloat162_rn(lx, ly);
    __nv_bfloat162 e1 = __floats2bfloat162_rn(lz, lw);
    uint2 hh; hh.x = *(uint32_t*)&h0; hh.y = *(uint32_t*)&h1;
    uint2 ll; ll.x = *(uint32_t*)&e0; ll.y = *(uint32_t*)&e1;
    *(uint2*)base_hi = hh;
    *(uint2*)base_lo = ll;
}

__global__ __launch_bounds__(THREADS, 1)
void attn_mma_kernel(const float* __restrict__ qg, const float* __restrict__ kg,
                     const float* __restrict__ vg, const float* __restrict__ ag,
                     float* __restrict__ out, float* __restrict__ attnw, int write_attn) {
    extern __shared__ __align__(16) char sm[];
    const uint32_t sb = s2u(sm);
    const int tid = threadIdx.x, lane = tid & 31, wid = tid >> 5;
    const int wm = wid >> 1, wn = wid & 1;
    const int g = lane >> 2, qd = lane & 3;
    const int bx = blockIdx.x;
    const int qt = bx & 3, hd = (bx >> 2) & 7, b = bx >> 5;
    const int l0 = qt * MT;

    const size_t kvstride4 = (size_t)HH * NTOK * DH / 4;  // float4 stride between blocks
    const size_t kvoff0 = ((size_t)(b * NBLK) * HH + hd) * (NTOK * DH);
    const float4* kg4b = (const float4*)(kg + kvoff0);
    const float4* vg4b = (const float4*)(vg + kvoff0);
    float4* stg = (float4*)(sm + OFF_STG);

    // ---- Q load + split (scale = 1/8 * log2e folded) ----
    {
        const float SC = 0.125f * 1.4426950408889634f;
        const float4* qg4 = (const float4*)(qg + (size_t)((b * HH + hd) * LQ + l0) * DH);
#pragma unroll
        for (int i = 0; i < 8; i++) {
            int idx = tid + i * THREADS;
            int row = idx >> 4, c4 = idx & 15;
            float4 v = qg4[idx];
            v.x *= SC; v.y *= SC; v.z *= SC; v.w *= SC;
            char* base = sm + row * RB + c4 * 8;
            split_store(v, base + OFF_QH, base + OFF_QL);
        }
    }
    // ---- block 0 K/V split into buffer 0 (prologue LDG, 4-chunk batches) ----
#pragma unroll
    for (int c = 0; c < 2; c++) {
        float4 buf[4];
#pragma unroll
        for (int j = 0; j < 4; j++) buf[j] = kg4b[tid + (c * 4 + j) * THREADS];
#pragma unroll
        for (int j = 0; j < 4; j++) {
            int idx = tid + (c * 4 + j) * THREADS;
            int row = idx >> 4, c4 = idx & 15;
            char* base = sm + OFF_T0 + row * RB + c4 * 8;
            split_store(buf[j], base, base + TILE);
        }
    }
#pragma unroll
    for (int c = 0; c < 2; c++) {
        float4 buf[4];
#pragma unroll
        for (int j = 0; j < 4; j++) buf[j] = vg4b[tid + (c * 4 + j) * THREADS];
#pragma unroll
        for (int j = 0; j < 4; j++) {
            int idx = tid + (c * 4 + j) * THREADS;
            int row = idx >> 4, c4 = idx & 15;
            char* base = sm + OFF_T0 + row * RB + c4 * 8;
            split_store(buf[j], base + 2 * TILE, base + 3 * TILE);
        }
    }
    __syncthreads();

    // ldmatrix lane-offsets
    const uint32_t aQ = sb + OFF_QH +
        (uint32_t)((wm * 32 + (lane & 15)) * RB + (lane >> 4) * 16);
    const uint32_t bKoff = (uint32_t)((wn * 64 + ((lane >> 4) & 1) * 8 + (lane & 7)) * RB +
                                      ((lane >> 3) & 1) * 16);
    const uint32_t bVoff = (uint32_t)((wn * 64 + (lane & 15)) * RB + ((lane >> 4) & 1) * 16);

    float* rs = (float*)(sm + OFF_RS);
    const float* asbase = ag + (size_t)((b * HH + hd) * LQ + l0 + wm * 32 + g) * NBLK;
    float* awbase = attnw + (size_t)((b * HH + hd) * LQ + l0 + wm * 32 + g) * (NBLK * NTOK)
                    + wn * 64 + 2 * qd;

    float acc2[2][8][4];
#pragma unroll
    for (int mi = 0; mi < 2; mi++)
#pragma unroll
        for (int ni = 0; ni < 8; ni++)
#pragma unroll
            for (int j = 0; j < 4; j++) acc2[mi][ni][j] = 0.f;

    // exp2 constants
    const ull MAGIC2 = 0x4B4000004B400000ULL;
    const ull NMAGIC2 = 0xCB400000CB400000ULL;
    const ull NEG1_2 = 0xBF800000BF800000ULL;
    const ull ONE2 = 0x3F8000003F800000ULL;
    const ull C5 = pack2(0.0013333558f, 0.0013333558f);
    const ull C4 = pack2(0.0096181291f, 0.0096181291f);
    const ull C3 = pack2(0.0555041087f, 0.0555041087f);
    const ull C2 = pack2(0.2402265070f, 0.2402265070f);
    const ull C1 = pack2(0.6931471806f, 0.6931471806f);

    for (int nb = 0; nb < NBLK; nb++) {
        const int p = nb & 1;
        const uint32_t tb = (p ? OFF_T1 : OFF_T0);
        char* tnext = sm + (p ? OFF_T0 : OFF_T1);
        const uint32_t bKc = sb + tb + bKoff;
        const uint32_t bVc = sb + tb + 2 * TILE + bVoff;
        const bool more = (nb + 1 < NBLK);

        // ---- issue cp.async K(nb+1) -> stage (0 register cost) ----
        if (more) {
            const float4* kp = kg4b + (size_t)(nb + 1) * kvstride4;
#pragma unroll
            for (int j = 0; j < 8; j++) {
                int pos = tid + j * THREADS;
                cpa16(sb + OFF_STG + pos * 16, kp + pos);
            }
            CP_COMMIT();
        }

        // ---- GEMM1: S(m32 x t64 per warp) = Q @ K^T, 3 bf16 products ----
        float acc[2][8][4];
#pragma unroll
        for (int mi = 0; mi < 2; mi++)
#pragma unroll
            for (int ni = 0; ni < 8; ni++)
#pragma unroll
                for (int j = 0; j < 4; j++) acc[mi][ni][j] = 0.f;

#pragma unroll
        for (int ks = 0; ks < 4; ks++) {
            uint32_t Ah[2][4], Al[2][4];
#pragma unroll
            for (int mi = 0; mi < 2; mi++) {
                ldsm4(Ah[mi], aQ + mi * (16 * RB) + ks * 32);
                ldsm4(Al[mi], aQ + TILE + mi * (16 * RB) + ks * 32);
            }
#pragma unroll
            for (int np = 0; np < 4; np++) {
                uint32_t bh[4], bl[4];
                ldsm4(bh, bKc + np * (16 * RB) + ks * 32);
                ldsm4(bl, bKc + TILE + np * (16 * RB) + ks * 32);
#pragma unroll
                for (int mi = 0; mi < 2; mi++) {
                    mma16816(acc[mi][2 * np], Ah[mi], bh);
                    mma16816(acc[mi][2 * np], Ah[mi], bl);
                    mma16816(acc[mi][2 * np], Al[mi], bh);
                    mma16816(acc[mi][2 * np + 1], Ah[mi], bh + 2);
                    mma16816(acc[mi][2 * np + 1], Ah[mi], bl + 2);
                    mma16816(acc[mi][2 * np + 1], Al[mi], bh + 2);
                }
            }
        }

        // ---- softmax ----
        float coef[2][2];
#pragma unroll
        for (int mi = 0; mi < 2; mi++)
#pragma unroll
            for (int h2 = 0; h2 < 2; h2++) {
                ull s2 = 0ULL;
#pragma unroll
                for (int ni = 0; ni < 8; ni++) {
                    ull y2 = pack2(acc[mi][ni][2 * h2], acc[mi][ni][2 * h2 + 1]);
                    ull t2 = add2(y2, MAGIC2);
                    ull u2 = add2(t2, NMAGIC2);
                    ull f2 = fma2(u2, NEG1_2, y2);
                    ull p2 = fma2(C5, f2, C4);
                    p2 = fma2(p2, f2, C3);
                    p2 = fma2(p2, f2, C2);
                    p2 = fma2(p2, f2, C1);
                    p2 = fma2(p2, f2, ONE2);
                    uint32_t tlo = (uint32_t)t2, thi = (uint32_t)(t2 >> 32);
                    uint32_t plo = (uint32_t)p2, phi = (uint32_t)(p2 >> 32);
                    float e0 = __int_as_float(plo + (tlo << 23));
                    float e1 = __int_as_float(phi + (thi << 23));
                    acc[mi][ni][2 * h2] = e0;
                    acc[mi][ni][2 * h2 + 1] = e1;
                    s2 = add2(s2, pack2(e0, e1));
                }
                float slo, shi;
                unpack2(s2, slo, shi);
                float s = slo + shi;
                s += __shfl_xor_sync(0xffffffffu, s, 1);
                s += __shfl_xor_sync(0xffffffffu, s, 2);
                if (qd == 0) rs[(wm * 32 + mi * 16 + g + 8 * h2) * 2 + wn] = s;
            }
        barpair(1 + wm);
#pragma unroll
        for (int mi = 0; mi < 2; mi++)
#pragma unroll
            for (int h2 = 0; h2 < 2; h2++) {
                int r = wm * 32 + mi * 16 + g + 8 * h2;
                float tot = rs[r * 2] + rs[r * 2 + 1];
                coef[mi][h2] = __fdividef(__ldg(asbase + (mi * 16 + 8 * h2) * NBLK + nb), tot);
            }

        if (more) CP_WAIT0();  // K(nb+1) in stage (per-thread visibility sufficient)

        // ---- GEMM2 with interleaved stage-split ----
        float* awp = awbase + nb * NTOK;
#pragma unroll
        for (int kt = 0; kt < 4; kt++) {
            // W hi/lo fragments for this kt
            uint32_t Awh[2][4], Awl[2][4];
#pragma unroll
            for (int mi = 0; mi < 2; mi++) {
                ull c2h0 = pack2(coef[mi][0], coef[mi][0]);
                ull c2h1 = pack2(coef[mi][1], coef[mi][1]);
#pragma unroll
                for (int half = 0; half < 2; half++) {
                    int ni = 2 * kt + half;
                    ull w0 = mul2(pack2(acc[mi][ni][0], acc[mi][ni][1]), c2h0);
                    ull w1 = mul2(pack2(acc[mi][ni][2], acc[mi][ni][3]), c2h1);
                    if (write_attn) {
                        *(ull*)(awp + (mi * 16) * (NBLK * NTOK) + ni * 8) = w0;
                        *(ull*)(awp + (mi * 16 + 8) * (NBLK * NTOK) + ni * 8) = w1;
                    }
                    float x0, x1, y0, y1;
                    unpack2(w0, x0, x1);
                    unpack2(w1, y0, y1);
                    uint32_t hb0, hb1;
                    asm("cvt.rn.bf16x2.f32 %0, %1, %2;" : "=r"(hb0) : "f"(x1), "f"(x0));
                    asm("cvt.rn.bf16x2.f32 %0, %1, %2;" : "=r"(hb1) : "f"(y1), "f"(y0));
                    Awh[mi][half * 2] = hb0;
                    Awh[mi][half * 2 + 1] = hb1;
                    ull hf0 = pack2(__int_as_float(hb0 << 16), __int_as_float(hb0 & 0xffff0000u));
                    ull hf1 = pack2(__int_as_float(hb1 << 16), __int_as_float(hb1 & 0xffff0000u));
                    ull l0v = fma2(hf0, NEG1_2, w0);
                    ull l1v = fma2(hf1, NEG1_2, w1);
                    float q0, q1, q2, q3;
                    unpack2(l0v, q0, q1);
                    unpack2(l1v, q2, q3);
                    uint32_t lb0, lb1;
                    asm("cvt.rn.bf16x2.f32 %0, %1, %2;" : "=r"(lb0) : "f"(q1), "f"(q0));
                    asm("cvt.rn.bf16x2.f32 %0, %1, %2;" : "=r"(lb1) : "f"(q3), "f"(q2));
                    Awl[mi][half * 2] = lb0;
                    Awl[mi][half * 2 + 1] = lb1;
                }
            }

            // stage LDS: kt 0-1 -> K chunks; kt 3 -> V chunks (first half)
            float4 sbuf[4];
            if (more && kt < 2) {
#pragma unroll
                for (int j = 0; j < 4; j++) sbuf[j] = stg[tid + (kt * 4 + j) * THREADS];
            }
            if (more && kt == 3) {
#pragma unroll
                for (int j = 0; j < 4; j++) sbuf[j] = stg[tid + j * THREADS];
            }

#pragma unroll
            for (int np = 0; np < 4; np++) {
                uint32_t vh[4], vl[4];
                ldsm4t(vh, bVc + kt * (16 * RB) + np * 32);
                ldsm4t(vl, bVc + TILE + kt * (16 * RB) + np * 32);
#pragma unroll
                for (int mi = 0; mi < 2; mi++) {
                    mma16816(acc2[mi][2 * np], Awh[mi], vh);
                    mma16816(acc2[mi][2 * np], Awh[mi], vl);
                    mma16816(acc2[mi][2 * np], Awl[mi], vh);
                    mma16816(acc2[mi][2 * np + 1], Awh[mi], vh + 2);
                    mma16816(acc2[mi][2 * np + 1], Awh[mi], vl + 2);
                    mma16816(acc2[mi][2 * np + 1], Awl[mi], vh + 2);
                }
            }

            // split-store staged chunks into next-buffer tiles
            if (more && kt < 2) {
#pragma unroll
                for (int j = 0; j < 4; j++) {
                    int idx = tid + (kt * 4 + j) * THREADS;
                    int row = idx >> 4, c4 = idx & 15;
                    char* base = tnext + row * RB + c4 * 8;
                    split_store(sbuf[j], base, base + TILE);  // K hi/lo
                }
            }
            if (more && kt == 1) {  // all K stage reads done (program order) -> stage V
                const float4* vp = vg4b + (size_t)(nb + 1) * kvstride4;
#pragma unroll
                for (int j = 0; j < 8; j++) {
                    int pos = tid + j * THREADS;
                    cpa16(sb + OFF_STG + pos * 16, vp + pos);
                }
                CP_COMMIT();
            }
            if (more && kt == 2) CP_WAIT0();  // V(nb+1) arrived
            if (more && kt == 3) {
#pragma unroll
                for (int j = 0; j < 4; j++) {
                    int idx = tid + j * THREADS;
                    int row = idx >> 4, c4 = idx & 15;
                    char* base = tnext + row * RB + c4 * 8;
                    split_store(sbuf[j], base + 2 * TILE, base + 3 * TILE);  // V hi/lo
                }
                // second half of V
                float4 sb2[4];
#pragma unroll
                for (int j = 0; j < 4; j++) sb2[j] = stg[tid + (4 + j) * THREADS];
#pragma unroll
                for (int j = 0; j < 4; j++) {
                    int idx = tid + (4 + j) * THREADS;
                    int row = idx >> 4, c4 = idx & 15;
                    char* base = tnext + row * RB + c4 * 8;
                    split_store(sb2[j], base + 2 * TILE, base + 3 * TILE);
                }
            }
        }
        __syncthreads();  // buf(1-p) complete; everyone done with buf(p) + stage
    }

    // ---- pair reduction (wn=0 + wn=1) via T0 scratch, then store out ----
    float* red = (float*)(sm + OFF_T0) + wm * (32 * RED_STR);
    if (wn == 1) {
#pragma unroll
        for (int mi = 0; mi < 2; mi++)
#pragma unroll
            for (int h2 = 0; h2 < 2; h2++)
#pragma unroll
                for (int ni = 0; ni < 8; ni++) {
                    int row = mi * 16 + g + 8 * h2;
                    float2 pv;
                    pv.x = acc2[mi][ni][2 * h2];
                    pv.y = acc2[mi][ni][2 * h2 + 1];
                    *(float2*)(red + row * RED_STR + ni * 8 + 2 * qd) = pv;
                }
    }
    barpair(1 + wm);
    if (wn == 0) {
#pragma unroll
        for (int mi = 0; mi < 2; mi++)
#pragma unroll
            for (int h2 = 0; h2 < 2; h2++) {
                int row = mi * 16 + g + 8 * h2;
                float* op = out + (size_t)(b * LQ + l0 + wm * 32 + row) * (HH * DH) + hd * DH;
#pragma unroll
                for (int ni = 0; ni < 8; ni++) {
                    float2 o = *(float2*)(red + row * RED_STR + ni * 8 + 2 * qd);
                    float2 pv;
                    pv.x = acc2[mi][ni][2 * h2] + o.x;
                    pv.y = acc2[mi][ni][2 * h2 + 1] + o.y;
                    *(float2*)(op + ni * 8 + 2 * qd) = pv;
                }
            }
    }
}

extern "C" void kernel_launch(void* const* d_in, const int* in_sizes, int n_in,
                              void* d_out, int out_size) {
    (void)in_sizes; (void)n_in;
    const float* q = (const float*)d_in[0];
    const float* k = (const float*)d_in[1];
    const float* v = (const float*)d_in[2];
    const float* a = (const float*)d_in[3];
    float* out = (float*)d_out;

    int write_attn = ((size_t)out_size >= OUT_ELEMS + ATTN_ELEMS) ? 1 : 0;
    float* attnw = out + OUT_ELEMS;

    cudaFuncSetAttribute(attn_mma_kernel,
                         cudaFuncAttributeMaxDynamicSharedMemorySize, SMEM_BYTES);

    dim3 grid(BB * HH * (LQ / MT));  // 128
    attn_mma_kernel<<<grid, THREADS, SMEM_BYTES>>>(q, k, v, a, out, attnw, write_attn);
}

// round 16
// speedup vs baseline: 1.3133x; 1.3133x over previous
#include <cuda_runtime.h>
#include <cuda_fp16.h>
#include <cstdint>

#define BB 4
#define HH 8
#define LQ 512
#define NBLK 32
#define NTOK 128
#define DH 64
#define MT 128
#define THREADS 256

#define OUT_ELEMS  (BB * LQ * HH * DH)
#define ATTN_ELEMS ((size_t)BB * HH * LQ * NBLK * NTOK)

#define QSTR 72          // fp16 elements per row (64 + 8 pad)
#define RB (QSTR * 2)    // 144 bytes per row
#define TILE (128 * RB)  // 18432 bytes per 128-row tile

// smem byte offsets: Qh, Ql, Kh, Vh tiles + rowsums + 64KB fp32 stage
#define OFF_QH 0
#define OFF_QL (OFF_QH + TILE)
#define OFF_KH (OFF_QL + TILE)
#define OFF_VH (OFF_KH + TILE)
#define OFF_RS (OFF_VH + TILE)
#define OFF_STG (OFF_RS + 1024)
#define SMEM_BYTES (OFF_STG + 65536)   // 140288

#define RED_STR 66

typedef unsigned long long ull;

__device__ __forceinline__ uint32_t s2u(const void* p) {
    uint32_t a;
    asm("{ .reg .u64 t; cvta.to.shared.u64 t, %1; cvt.u32.u64 %0, t; }" : "=r"(a) : "l"(p));
    return a;
}
__device__ __forceinline__ ull pack2(float x, float y) {
    ull r; asm("mov.b64 %0, {%1,%2};" : "=l"(r) : "f"(x), "f"(y)); return r;
}
__device__ __forceinline__ void unpack2(ull v, float& x, float& y) {
    asm("mov.b64 {%0,%1}, %2;" : "=f"(x), "=f"(y) : "l"(v));
}
__device__ __forceinline__ ull add2(ull a, ull b) {
    ull d; asm("add.rn.f32x2 %0, %1, %2;" : "=l"(d) : "l"(a), "l"(b)); return d;
}
__device__ __forceinline__ ull mul2(ull a, ull b) {
    ull d; asm("mul.rn.f32x2 %0, %1, %2;" : "=l"(d) : "l"(a), "l"(b)); return d;
}
__device__ __forceinline__ ull fma2(ull a, ull b, ull c) {
    ull d; asm("fma.rn.f32x2 %0, %1, %2, %3;" : "=l"(d) : "l"(a), "l"(b), "l"(c)); return d;
}
__device__ __forceinline__ void ldsm4(uint32_t* r, uint32_t a) {
    asm volatile("ldmatrix.sync.aligned.m8n8.x4.shared.b16 {%0,%1,%2,%3}, [%4];"
                 : "=r"(r[0]), "=r"(r[1]), "=r"(r[2]), "=r"(r[3]) : "r"(a));
}
__device__ __forceinline__ void ldsm4t(uint32_t* r, uint32_t a) {
    asm volatile("ldmatrix.sync.aligned.m8n8.x4.trans.shared.b16 {%0,%1,%2,%3}, [%4];"
                 : "=r"(r[0]), "=r"(r[1]), "=r"(r[2]), "=r"(r[3]) : "r"(a));
}
__device__ __forceinline__ void mma16816(float* c, const uint32_t* a, const uint32_t* b) {
    asm volatile(
        "mma.sync.aligned.m16n8k16.row.col.f32.f16.f16.f32 "
        "{%0,%1,%2,%3}, {%4,%5,%6,%7}, {%8,%9}, {%0,%1,%2,%3};"
        : "+f"(c[0]), "+f"(c[1]), "+f"(c[2]), "+f"(c[3])
        : "r"(a[0]), "r"(a[1]), "r"(a[2]), "r"(a[3]), "r"(b[0]), "r"(b[1]));
}
__device__ __forceinline__ void cpa16(uint32_t dst, const void* src) {
    asm volatile("cp.async.cg.shared.global [%0], [%1], 16;" :: "r"(dst), "l"(src));
}
#define CP_COMMIT() asm volatile("cp.async.commit_group;" ::: "memory")
#define CP_WAIT0()  asm volatile("cp.async.wait_group 0;" ::: "memory")
__device__ __forceinline__ void barpair(int id) {
    asm volatile("bar.sync %0, 64;" :: "r"(id) : "memory");
}

// convert fp32 float4 -> 4 fp16, store 8B
__device__ __forceinline__ void cvt16_store(float4 v, char* base) {
    __half2 a = __floats2half2_rn(v.x, v.y);
    __half2 b = __floats2half2_rn(v.z, v.w);
    uint2 u; u.x = *(uint32_t*)&a; u.y = *(uint32_t*)&b;
    *(uint2*)base = u;
}
// split fp32 float4 into fp16 hi + fp16 lo (residual), store 8B each
__device__ __forceinline__ void split_store16(float4 v, char* bh, char* bl) {
    __half2 h0 = __floats2half2_rn(v.x, v.y);
    __half2 h1 = __floats2half2_rn(v.z, v.w);
    float2 f0 = __half22float2(h0);
    float2 f1 = __half22float2(h1);
    __half2 l0 = __floats2half2_rn(v.x - f0.x, v.y - f0.y);
    __half2 l1 = __floats2half2_rn(v.z - f1.x, v.w - f1.y);
    uint2 hh; hh.x = *(uint32_t*)&h0; hh.y = *(uint32_t*)&h1;
    uint2 ll; ll.x = *(uint32_t*)&l0; ll.y = *(uint32_t*)&l1;
    *(uint2*)bh = hh;
    *(uint2*)bl = ll;
}

__global__ __launch_bounds__(THREADS, 1)
void attn_mma_kernel(const float* __restrict__ qg, const float* __restrict__ kg,
                     const float* __restrict__ vg, const float* __restrict__ ag,
                     float* __restrict__ out, float* __restrict__ attnw, int write_attn) {
    extern __shared__ __align__(16) char sm[];
    const uint32_t sb = s2u(sm);
    const int tid = threadIdx.x, lane = tid & 31, wid = tid >> 5;
    const int wm = wid >> 1, wn = wid & 1;
    const int g = lane >> 2, qd = lane & 3;
    const int bx = blockIdx.x;
    const int qt = bx & 3, hd = (bx >> 2) & 7, b = bx >> 5;
    const int l0 = qt * MT;

    const size_t kvstride4 = (size_t)HH * NTOK * DH / 4;
    const size_t kvoff0 = ((size_t)(b * NBLK) * HH + hd) * (NTOK * DH);
    const float4* kg4b = (const float4*)(kg + kvoff0);
    const float4* vg4b = (const float4*)(vg + kvoff0);

    // ---- prefetch K/V block 0 into stage ----
    {
#pragma unroll
        for (int i = 0; i < 8; i++) {
            int idx = tid + i * THREADS;
            cpa16(sb + OFF_STG + idx * 16, kg4b + idx);
            cpa16(sb + OFF_STG + 32768 + idx * 16, vg4b + idx);
        }
        CP_COMMIT();
    }

    // ---- Q load + split to fp16 hi/lo (scale = 1/8 * log2e folded) ----
    {
        const float SC = 0.125f * 1.4426950408889634f;
        const float4* qg4 = (const float4*)(qg + (size_t)((b * HH + hd) * LQ + l0) * DH);
#pragma unroll
        for (int i = 0; i < 8; i++) {
            int idx = tid + i * THREADS;
            int row = idx >> 4, c4 = idx & 15;
            float4 v = qg4[idx];
            v.x *= SC; v.y *= SC; v.z *= SC; v.w *= SC;
            char* base = sm + row * RB + c4 * 8;
            split_store16(v, base + OFF_QH, base + OFF_QL);
        }
    }

    // ldmatrix base addresses
    const uint32_t aQ = sb + OFF_QH +
        (uint32_t)((wm * 32 + (lane & 15)) * RB + (lane >> 4) * 16);
    const uint32_t bK = sb + OFF_KH +
        (uint32_t)((wn * 64 + ((lane >> 4) & 1) * 8 + (lane & 7)) * RB + ((lane >> 3) & 1) * 16);
    const uint32_t bV = sb + OFF_VH +
        (uint32_t)((wn * 64 + (lane & 15)) * RB + ((lane >> 4) & 1) * 16);

    float* rs = (float*)(sm + OFF_RS);
    const float* asbase = ag + (size_t)((b * HH + hd) * LQ + l0 + wm * 32 + g) * NBLK;
    float* awbase = attnw + (size_t)((b * HH + hd) * LQ + l0 + wm * 32 + g) * (NBLK * NTOK)
                    + wn * 64 + 2 * qd;

    float acc2[2][8][4];
#pragma unroll
    for (int mi = 0; mi < 2; mi++)
#pragma unroll
        for (int ni = 0; ni < 8; ni++)
#pragma unroll
            for (int j = 0; j < 4; j++) acc2[mi][ni][j] = 0.f;

    // exp2 constants
    const ull MAGIC2 = 0x4B4000004B400000ULL;
    const ull NMAGIC2 = 0xCB400000CB400000ULL;
    const ull NEG1_2 = 0xBF800000BF800000ULL;
    const ull ONE2 = 0x3F8000003F800000ULL;
    const ull C5 = pack2(0.0013333558f, 0.0013333558f);
    const ull C4 = pack2(0.0096181291f, 0.0096181291f);
    const ull C3 = pack2(0.0555041087f, 0.0555041087f);
    const ull C2 = pack2(0.2402265070f, 0.2402265070f);
    const ull C1 = pack2(0.6931471806f, 0.6931471806f);

    for (int nb = 0; nb < NBLK; nb++) {
        CP_WAIT0();
        __syncthreads();  // stage(nb) visible; GEMM2(nb-1) done with K/V tiles

        // ---- convert stage -> fp16 hi tiles (K, V; no lo tiles) ----
        {
            const float4* stK = (const float4*)(sm + OFF_STG);
            const float4* stV = (const float4*)(sm + OFF_STG + 32768);
#pragma unroll
            for (int i = 0; i < 8; i++) {
                int idx = tid + i * THREADS;
                int row = idx >> 4, c4 = idx & 15;
                char* base = sm + row * RB + c4 * 8;
                cvt16_store(stK[idx], base + OFF_KH);
                cvt16_store(stV[idx], base + OFF_VH);
            }
        }
        __syncthreads();  // tiles ready; stage fully consumed

        // ---- prefetch next block ----
        if (nb + 1 < NBLK) {
            const float4* kp = kg4b + (size_t)(nb + 1) * kvstride4;
            const float4* vp = vg4b + (size_t)(nb + 1) * kvstride4;
#pragma unroll
            for (int i = 0; i < 8; i++) {
                int idx = tid + i * THREADS;
                cpa16(sb + OFF_STG + idx * 16, kp + idx);
                cpa16(sb + OFF_STG + 32768 + idx * 16, vp + idx);
            }
        }
        CP_COMMIT();

        // ---- GEMM1: S(m32 x t64 per warp) = (Qh+Ql) @ Kh^T, 2 fp16 products ----
        float acc[2][8][4];
#pragma unroll
        for (int mi = 0; mi < 2; mi++)
#pragma unroll
            for (int ni = 0; ni < 8; ni++)
#pragma unroll
                for (int j = 0; j < 4; j++) acc[mi][ni][j] = 0.f;

#pragma unroll
        for (int ks = 0; ks < 4; ks++) {
            uint32_t Ah[2][4], Al[2][4];
#pragma unroll
            for (int mi = 0; mi < 2; mi++) {
                ldsm4(Ah[mi], aQ + mi * (16 * RB) + ks * 32);
                ldsm4(Al[mi], aQ + TILE + mi * (16 * RB) + ks * 32);
            }
#pragma unroll
            for (int np = 0; np < 4; np++) {
                uint32_t bh[4];
                ldsm4(bh, bK + np * (16 * RB) + ks * 32);
#pragma unroll
                for (int mi = 0; mi < 2; mi++) {
                    mma16816(acc[mi][2 * np], Ah[mi], bh);
                    mma16816(acc[mi][2 * np], Al[mi], bh);
                    mma16816(acc[mi][2 * np + 1], Ah[mi], bh + 2);
                    mma16816(acc[mi][2 * np + 1], Al[mi], bh + 2);
                }
            }
        }

        // ---- softmax: e = 2^S, partial rowsums over this warp's t64 ----
        float coef[2][2];
#pragma unroll
        for (int mi = 0; mi < 2; mi++)
#pragma unroll
            for (int h2 = 0; h2 < 2; h2++) {
                ull s2 = 0ULL;
#pragma unroll
                for (int ni = 0; ni < 8; ni++) {
                    ull y2 = pack2(acc[mi][ni][2 * h2], acc[mi][ni][2 * h2 + 1]);
                    ull t2 = add2(y2, MAGIC2);
                    ull u2 = add2(t2, NMAGIC2);
                    ull f2 = fma2(u2, NEG1_2, y2);
                    ull p2 = fma2(C5, f2, C4);
                    p2 = fma2(p2, f2, C3);
                    p2 = fma2(p2, f2, C2);
                    p2 = fma2(p2, f2, C1);
                    p2 = fma2(p2, f2, ONE2);
                    uint32_t tlo = (uint32_t)t2, thi = (uint32_t)(t2 >> 32);
                    uint32_t plo = (uint32_t)p2, phi = (uint32_t)(p2 >> 32);
                    float e0 = __int_as_float(plo + (tlo << 23));
                    float e1 = __int_as_float(phi + (thi << 23));
                    acc[mi][ni][2 * h2] = e0;
                    acc[mi][ni][2 * h2 + 1] = e1;
                    s2 = add2(s2, pack2(e0, e1));
                }
                float slo, shi;
                unpack2(s2, slo, shi);
                float s = slo + shi;
                s += __shfl_xor_sync(0xffffffffu, s, 1);
                s += __shfl_xor_sync(0xffffffffu, s, 2);
                if (qd == 0) rs[(wm * 32 + mi * 16 + g + 8 * h2) * 2 + wn] = s;
            }
        barpair(1 + wm);
#pragma unroll
        for (int mi = 0; mi < 2; mi++)
#pragma unroll
            for (int h2 = 0; h2 < 2; h2++) {
                int r = wm * 32 + mi * 16 + g + 8 * h2;
                float tot = rs[r * 2] + rs[r * 2 + 1];
                coef[mi][h2] = __fdividef(__ldg(asbase + (mi * 16 + 8 * h2) * NBLK + nb), tot);
            }

        // ---- GEMM2: out += (Wh+Wl) @ Vh, 2 fp16 products; attn_w en route ----
        float* awp = awbase + nb * NTOK;
#pragma unroll
        for (int kt = 0; kt < 4; kt++) {
            uint32_t Awh[2][4], Awl[2][4];
#pragma unroll
            for (int mi = 0; mi < 2; mi++) {
                ull c2h0 = pack2(coef[mi][0], coef[mi][0]);
                ull c2h1 = pack2(coef[mi][1], coef[mi][1]);
#pragma unroll
                for (int half = 0; half < 2; half++) {
                    int ni = 2 * kt + half;
                    ull w0 = mul2(pack2(acc[mi][ni][0], acc[mi][ni][1]), c2h0);  // row g
                    ull w1 = mul2(pack2(acc[mi][ni][2], acc[mi][ni][3]), c2h1);  // row g+8
                    if (write_attn) {
                        *(ull*)(awp + (mi * 16) * (NBLK * NTOK) + ni * 8) = w0;
                        *(ull*)(awp + (mi * 16 + 8) * (NBLK * NTOK) + ni * 8) = w1;
                    }
                    float x0, x1, y0, y1;
                    unpack2(w0, x0, x1);
                    unpack2(w1, y0, y1);
                    __half2 h2a = __floats2half2_rn(x0, x1);
                    __half2 h2b = __floats2half2_rn(y0, y1);
                    Awh[mi][half * 2] = *(uint32_t*)&h2a;
                    Awh[mi][half * 2 + 1] = *(uint32_t*)&h2b;
                    float2 fa = __half22float2(h2a);
                    float2 fb = __half22float2(h2b);
                    __half2 l2a = __floats2half2_rn(x0 - fa.x, x1 - fa.y);
                    __half2 l2b = __floats2half2_rn(y0 - fb.x, y1 - fb.y);
                    Awl[mi][half * 2] = *(uint32_t*)&l2a;
                    Awl[mi][half * 2 + 1] = *(uint32_t*)&l2b;
                }
            }
#pragma unroll
            for (int np = 0; np < 4; np++) {
                uint32_t vh[4];
                ldsm4t(vh, bV + kt * (16 * RB) + np * 32);
#pragma unroll
                for (int mi = 0; mi < 2; mi++) {
                    mma16816(acc2[mi][2 * np], Awh[mi], vh);
                    mma16816(acc2[mi][2 * np], Awl[mi], vh);
                    mma16816(acc2[mi][2 * np + 1], Awh[mi], vh + 2);
                    mma16816(acc2[mi][2 * np + 1], Awl[mi], vh + 2);
                }
            }
        }
    }

    // ---- pair reduction (wn=0 + wn=1) via stage scratch, then store out ----
    float* red = (float*)(sm + OFF_STG) + wm * (32 * RED_STR);
    if (wn == 1) {
#pragma unroll
        for (int mi = 0; mi < 2; mi++)
#pragma unroll
            for (int h2 = 0; h2 < 2; h2++)
#pragma unroll
                for (int ni = 0; ni < 8; ni++) {
                    int row = mi * 16 + g + 8 * h2;
                    float2 pv;
                    pv.x = acc2[mi][ni][2 * h2];
                    pv.y = acc2[mi][ni][2 * h2 + 1];
                    *(float2*)(red + row * RED_STR + ni * 8 + 2 * qd) = pv;
                }
    }
    barpair(1 + wm);
    if (wn == 0) {
#pragma unroll
        for (int mi = 0; mi < 2; mi++)
#pragma unroll
            for (int h2 = 0; h2 < 2; h2++) {
                int row = mi * 16 + g + 8 * h2;
                float* op = out + (size_t)(b * LQ + l0 + wm * 32 + row) * (HH * DH) + hd * DH;
#pragma unroll
                for (int ni = 0; ni < 8; ni++) {
                    float2 o = *(float2*)(red + row * RED_STR + ni * 8 + 2 * qd);
                    float2 pv;
                    pv.x = acc2[mi][ni][2 * h2] + o.x;
                    pv.y = acc2[mi][ni][2 * h2 + 1] + o.y;
                    *(float2*)(op + ni * 8 + 2 * qd) = pv;
                }
            }
    }
}

extern "C" void kernel_launch(void* const* d_in, const int* in_sizes, int n_in,
                              void* d_out, int out_size) {
    (void)in_sizes; (void)n_in;
    const float* q = (const float*)d_in[0];
    const float* k = (const float*)d_in[1];
    const float* v = (const float*)d_in[2];
    const float* a = (const float*)d_in[3];
    float* out = (float*)d_out;

    int write_attn = ((size_t)out_size >= OUT_ELEMS + ATTN_ELEMS) ? 1 : 0;
    float* attnw = out + OUT_ELEMS;

    cudaFuncSetAttribute(attn_mma_kernel,
                         cudaFuncAttributeMaxDynamicSharedMemorySize, SMEM_BYTES);

    dim3 grid(BB * HH * (LQ / MT));  // 128
    attn_mma_kernel<<<grid, THREADS, SMEM_BYTES>>>(q, k, v, a, out, attnw, write_attn);
}

// round 17
// speedup vs baseline: 1.4787x; 1.1259x over previous
#include <cuda_runtime.h>
#include <cuda_fp16.h>
#include <cstdint>

#define BB 4
#define HH 8
#define LQ 512
#define NBLK 32
#define NTOK 128
#define DH 64
#define MT 128
#define THREADS 256

#define OUT_ELEMS  (BB * LQ * HH * DH)
#define ATTN_ELEMS ((size_t)BB * HH * LQ * NBLK * NTOK)

#define QSTR 72          // fp16 elements per row (64 + 8 pad)
#define RB (QSTR * 2)    // 144 bytes per row
#define TILE (128 * RB)  // 18432 bytes per 128-row tile

// smem byte offsets: Qh, Kh, Vh tiles + rowsums + 64KB fp32 stage
#define OFF_QH 0
#define OFF_KH (OFF_QH + TILE)
#define OFF_VH (OFF_KH + TILE)
#define OFF_RS (OFF_VH + TILE)
#define OFF_STG (OFF_RS + 1024)
#define SMEM_BYTES (OFF_STG + 65536)   // 121856

#define RED_STR 66

typedef unsigned long long ull;

__device__ __forceinline__ uint32_t s2u(const void* p) {
    uint32_t a;
    asm("{ .reg .u64 t; cvta.to.shared.u64 t, %1; cvt.u32.u64 %0, t; }" : "=r"(a) : "l"(p));
    return a;
}
__device__ __forceinline__ ull pack2(float x, float y) {
    ull r; asm("mov.b64 %0, {%1,%2};" : "=l"(r) : "f"(x), "f"(y)); return r;
}
__device__ __forceinline__ void unpack2(ull v, float& x, float& y) {
    asm("mov.b64 {%0,%1}, %2;" : "=f"(x), "=f"(y) : "l"(v));
}
__device__ __forceinline__ ull add2(ull a, ull b) {
    ull d; asm("add.rn.f32x2 %0, %1, %2;" : "=l"(d) : "l"(a), "l"(b)); return d;
}
__device__ __forceinline__ ull mul2(ull a, ull b) {
    ull d; asm("mul.rn.f32x2 %0, %1, %2;" : "=l"(d) : "l"(a), "l"(b)); return d;
}
__device__ __forceinline__ ull fma2(ull a, ull b, ull c) {
    ull d; asm("fma.rn.f32x2 %0, %1, %2, %3;" : "=l"(d) : "l"(a), "l"(b), "l"(c)); return d;
}
__device__ __forceinline__ void ldsm4(uint32_t* r, uint32_t a) {
    asm volatile("ldmatrix.sync.aligned.m8n8.x4.shared.b16 {%0,%1,%2,%3}, [%4];"
                 : "=r"(r[0]), "=r"(r[1]), "=r"(r[2]), "=r"(r[3]) : "r"(a));
}
__device__ __forceinline__ void ldsm4t(uint32_t* r, uint32_t a) {
    asm volatile("ldmatrix.sync.aligned.m8n8.x4.trans.shared.b16 {%0,%1,%2,%3}, [%4];"
                 : "=r"(r[0]), "=r"(r[1]), "=r"(r[2]), "=r"(r[3]) : "r"(a));
}
__device__ __forceinline__ void mma16816(float* c, const uint32_t* a, const uint32_t* b) {
    asm volatile(
        "mma.sync.aligned.m16n8k16.row.col.f32.f16.f16.f32 "
        "{%0,%1,%2,%3}, {%4,%5,%6,%7}, {%8,%9}, {%0,%1,%2,%3};"
        : "+f"(c[0]), "+f"(c[1]), "+f"(c[2]), "+f"(c[3])
        : "r"(a[0]), "r"(a[1]), "r"(a[2]), "r"(a[3]), "r"(b[0]), "r"(b[1]));
}
__device__ __forceinline__ void cpa16(uint32_t dst, const void* src) {
    asm volatile("cp.async.cg.shared.global [%0], [%1], 16;" :: "r"(dst), "l"(src));
}
#define CP_COMMIT() asm volatile("cp.async.commit_group;" ::: "memory")
#define CP_WAIT0()  asm volatile("cp.async.wait_group 0;" ::: "memory")
__device__ __forceinline__ void barpair(int id) {
    asm volatile("bar.sync %0, 64;" :: "r"(id) : "memory");
}
__device__ __forceinline__ void stg_cs(void* p, ull v) {
    asm volatile("st.global.cs.b64 [%0], %1;" :: "l"(p), "l"(v) : "memory");
}

// convert fp32 float4 -> 4 fp16, store 8B
__device__ __forceinline__ void cvt16_store(float4 v, char* base) {
    __half2 a = __floats2half2_rn(v.x, v.y);
    __half2 b = __floats2half2_rn(v.z, v.w);
    uint2 u; u.x = *(uint32_t*)&a; u.y = *(uint32_t*)&b;
    *(uint2*)base = u;
}

__global__ __launch_bounds__(THREADS, 1)
void attn_mma_kernel(const float* __restrict__ qg, const float* __restrict__ kg,
                     const float* __restrict__ vg, const float* __restrict__ ag,
                     float* __restrict__ out, float* __restrict__ attnw, int write_attn) {
    extern __shared__ __align__(16) char sm[];
    const uint32_t sb = s2u(sm);
    const int tid = threadIdx.x, lane = tid & 31, wid = tid >> 5;
    const int wm = wid >> 1, wn = wid & 1;
    const int g = lane >> 2, qd = lane & 3;
    const int bx = blockIdx.x;
    const int qt = bx & 3, hd = (bx >> 2) & 7, b = bx >> 5;
    const int l0 = qt * MT;

    const size_t kvstride4 = (size_t)HH * NTOK * DH / 4;
    const size_t kvoff0 = ((size_t)(b * NBLK) * HH + hd) * (NTOK * DH);
    const float4* kg4b = (const float4*)(kg + kvoff0);
    const float4* vg4b = (const float4*)(vg + kvoff0);

    // ---- prefetch K/V block 0 into stage ----
    {
#pragma unroll
        for (int i = 0; i < 8; i++) {
            int idx = tid + i * THREADS;
            cpa16(sb + OFF_STG + idx * 16, kg4b + idx);
            cpa16(sb + OFF_STG + 32768 + idx * 16, vg4b + idx);
        }
        CP_COMMIT();
    }

    // ---- Q load + convert to fp16 (scale = 1/8 * log2e folded) ----
    {
        const float SC = 0.125f * 1.4426950408889634f;
        const float4* qg4 = (const float4*)(qg + (size_t)((b * HH + hd) * LQ + l0) * DH);
#pragma unroll
        for (int i = 0; i < 8; i++) {
            int idx = tid + i * THREADS;
            int row = idx >> 4, c4 = idx & 15;
            float4 v = qg4[idx];
            v.x *= SC; v.y *= SC; v.z *= SC; v.w *= SC;
            cvt16_store(v, sm + OFF_QH + row * RB + c4 * 8);
        }
    }

    // ldmatrix base addresses
    const uint32_t aQ = sb + OFF_QH +
        (uint32_t)((wm * 32 + (lane & 15)) * RB + (lane >> 4) * 16);
    const uint32_t bK = sb + OFF_KH +
        (uint32_t)((wn * 64 + ((lane >> 4) & 1) * 8 + (lane & 7)) * RB + ((lane >> 3) & 1) * 16);
    const uint32_t bV = sb + OFF_VH +
        (uint32_t)((wn * 64 + (lane & 15)) * RB + ((lane >> 4) & 1) * 16);

    float* rs = (float*)(sm + OFF_RS);
    const float* asbase = ag + (size_t)((b * HH + hd) * LQ + l0 + wm * 32 + g) * NBLK;
    float* awbase = attnw + (size_t)((b * HH + hd) * LQ + l0 + wm * 32 + g) * (NBLK * NTOK)
                    + wn * 64 + 2 * qd;

    float acc2[2][8][4];
#pragma unroll
    for (int mi = 0; mi < 2; mi++)
#pragma unroll
        for (int ni = 0; ni < 8; ni++)
#pragma unroll
            for (int j = 0; j < 4; j++) acc2[mi][ni][j] = 0.f;

    // exp2 constants
    const ull MAGIC2 = 0x4B4000004B400000ULL;
    const ull NMAGIC2 = 0xCB400000CB400000ULL;
    const ull NEG1_2 = 0xBF800000BF800000ULL;
    const ull ONE2 = 0x3F8000003F800000ULL;
    const ull C5 = pack2(0.0013333558f, 0.0013333558f);
    const ull C4 = pack2(0.0096181291f, 0.0096181291f);
    const ull C3 = pack2(0.0555041087f, 0.0555041087f);
    const ull C2 = pack2(0.2402265070f, 0.2402265070f);
    const ull C1 = pack2(0.6931471806f, 0.6931471806f);

    for (int nb = 0; nb < NBLK; nb++) {
        CP_WAIT0();
        __syncthreads();  // stage(nb) visible; GEMM2(nb-1) done with K/V tiles

        // ---- convert stage -> fp16 tiles ----
        {
            const float4* stK = (const float4*)(sm + OFF_STG);
            const float4* stV = (const float4*)(sm + OFF_STG + 32768);
#pragma unroll
            for (int i = 0; i < 8; i++) {
                int idx = tid + i * THREADS;
                int row = idx >> 4, c4 = idx & 15;
                char* base = sm + row * RB + c4 * 8;
                cvt16_store(stK[idx], base + OFF_KH);
                cvt16_store(stV[idx], base + OFF_VH);
            }
        }
        __syncthreads();  // tiles ready; stage fully consumed

        // ---- prefetch next block ----
        if (nb + 1 < NBLK) {
            const float4* kp = kg4b + (size_t)(nb + 1) * kvstride4;
            const float4* vp = vg4b + (size_t)(nb + 1) * kvstride4;
#pragma unroll
            for (int i = 0; i < 8; i++) {
                int idx = tid + i * THREADS;
                cpa16(sb + OFF_STG + idx * 16, kp + idx);
                cpa16(sb + OFF_STG + 32768 + idx * 16, vp + idx);
            }
        }
        CP_COMMIT();

        // ---- GEMM1: S(m32 x t64 per warp) = Qh @ Kh^T, 1 fp16 product ----
        float acc[2][8][4];
#pragma unroll
        for (int mi = 0; mi < 2; mi++)
#pragma unroll
            for (int ni = 0; ni < 8; ni++)
#pragma unroll
                for (int j = 0; j < 4; j++) acc[mi][ni][j] = 0.f;

#pragma unroll
        for (int ks = 0; ks < 4; ks++) {
            uint32_t Ah[2][4];
#pragma unroll
            for (int mi = 0; mi < 2; mi++)
                ldsm4(Ah[mi], aQ + mi * (16 * RB) + ks * 32);
#pragma unroll
            for (int np = 0; np < 4; np++) {
                uint32_t bh[4];
                ldsm4(bh, bK + np * (16 * RB) + ks * 32);
#pragma unroll
                for (int mi = 0; mi < 2; mi++) {
                    mma16816(acc[mi][2 * np], Ah[mi], bh);
                    mma16816(acc[mi][2 * np + 1], Ah[mi], bh + 2);
                }
            }
        }

        // ---- softmax: e = 2^S, partial rowsums over this warp's t64 ----
        float coef[2][2];
#pragma unroll
        for (int mi = 0; mi < 2; mi++)
#pragma unroll
            for (int h2 = 0; h2 < 2; h2++) {
                ull s2 = 0ULL;
#pragma unroll
                for (int ni = 0; ni < 8; ni++) {
                    ull y2 = pack2(acc[mi][ni][2 * h2], acc[mi][ni][2 * h2 + 1]);
                    ull t2 = add2(y2, MAGIC2);
                    ull u2 = add2(t2, NMAGIC2);
                    ull f2 = fma2(u2, NEG1_2, y2);
                    ull p2 = fma2(C5, f2, C4);
                    p2 = fma2(p2, f2, C3);
                    p2 = fma2(p2, f2, C2);
                    p2 = fma2(p2, f2, C1);
                    p2 = fma2(p2, f2, ONE2);
                    uint32_t tlo = (uint32_t)t2, thi = (uint32_t)(t2 >> 32);
                    uint32_t plo = (uint32_t)p2, phi = (uint32_t)(p2 >> 32);
                    float e0 = __int_as_float(plo + (tlo << 23));
                    float e1 = __int_as_float(phi + (thi << 23));
                    acc[mi][ni][2 * h2] = e0;
                    acc[mi][ni][2 * h2 + 1] = e1;
                    s2 = add2(s2, pack2(e0, e1));
                }
                float slo, shi;
                unpack2(s2, slo, shi);
                float s = slo + shi;
                s += __shfl_xor_sync(0xffffffffu, s, 1);
                s += __shfl_xor_sync(0xffffffffu, s, 2);
                if (qd == 0) rs[(wm * 32 + mi * 16 + g + 8 * h2) * 2 + wn] = s;
            }
        barpair(1 + wm);
#pragma unroll
        for (int mi = 0; mi < 2; mi++)
#pragma unroll
            for (int h2 = 0; h2 < 2; h2++) {
                int r = wm * 32 + mi * 16 + g + 8 * h2;
                float tot = rs[r * 2] + rs[r * 2 + 1];
                coef[mi][h2] = __fdividef(__ldg(asbase + (mi * 16 + 8 * h2) * NBLK + nb), tot);
            }

        // ---- GEMM2: out += Wh @ Vh, 1 fp16 product; attn_w (streaming) en route ----
        float* awp = awbase + nb * NTOK;
#pragma unroll
        for (int kt = 0; kt < 4; kt++) {
            uint32_t Awh[2][4];
#pragma unroll
            for (int mi = 0; mi < 2; mi++) {
                ull c2h0 = pack2(coef[mi][0], coef[mi][0]);
                ull c2h1 = pack2(coef[mi][1], coef[mi][1]);
#pragma unroll
                for (int half = 0; half < 2; half++) {
                    int ni = 2 * kt + half;
                    ull w0 = mul2(pack2(acc[mi][ni][0], acc[mi][ni][1]), c2h0);  // row g
                    ull w1 = mul2(pack2(acc[mi][ni][2], acc[mi][ni][3]), c2h1);  // row g+8
                    if (write_attn) {
                        stg_cs(awp + (mi * 16) * (NBLK * NTOK) + ni * 8, w0);
                        stg_cs(awp + (mi * 16 + 8) * (NBLK * NTOK) + ni * 8, w1);
                    }
                    float x0, x1, y0, y1;
                    unpack2(w0, x0, x1);
                    unpack2(w1, y0, y1);
                    __half2 h2a = __floats2half2_rn(x0, x1);
                    __half2 h2b = __floats2half2_rn(y0, y1);
                    Awh[mi][half * 2] = *(uint32_t*)&h2a;
                    Awh[mi][half * 2 + 1] = *(uint32_t*)&h2b;
                }
            }
#pragma unroll
            for (int np = 0; np < 4; np++) {
                uint32_t vh[4];
                ldsm4t(vh, bV + kt * (16 * RB) + np * 32);
#pragma unroll
                for (int mi = 0; mi < 2; mi++) {
                    mma16816(acc2[mi][2 * np], Awh[mi], vh);
                    mma16816(acc2[mi][2 * np + 1], Awh[mi], vh + 2);
                }
            }
        }
    }

    // ---- pair reduction (wn=0 + wn=1) via stage scratch, then store out ----
    float* red = (float*)(sm + OFF_STG) + wm * (32 * RED_STR);
    if (wn == 1) {
#pragma unroll
        for (int mi = 0; mi < 2; mi++)
#pragma unroll
            for (int h2 = 0; h2 < 2; h2++)
#pragma unroll
                for (int ni = 0; ni < 8; ni++) {
                    int row = mi * 16 + g + 8 * h2;
                    float2 pv;
                    pv.x = acc2[mi][ni][2 * h2];
                    pv.y = acc2[mi][ni][2 * h2 + 1];
                    *(float2*)(red + row * RED_STR + ni * 8 + 2 * qd) = pv;
                }
    }
    barpair(1 + wm);
    if (wn == 0) {
#pragma unroll
        for (int mi = 0; mi < 2; mi++)
#pragma unroll
            for (int h2 = 0; h2 < 2; h2++) {
                int row = mi * 16 + g + 8 * h2;
                float* op = out + (size_t)(b * LQ + l0 + wm * 32 + row) * (HH * DH) + hd * DH;
#pragma unroll
                for (int ni = 0; ni < 8; ni++) {
                    float2 o = *(float2*)(red + row * RED_STR + ni * 8 + 2 * qd);
                    float2 pv;
                    pv.x = acc2[mi][ni][2 * h2] + o.x;
                    pv.y = acc2[mi][ni][2 * h2 + 1] + o.y;
                    *(float2*)(op + ni * 8 + 2 * qd) = pv;
                }
            }
    }
}

extern "C" void kernel_launch(void* const* d_in, const int* in_sizes, int n_in,
                              void* d_out, int out_size) {
    (void)in_sizes; (void)n_in;
    const float* q = (const float*)d_in[0];
    const float* k = (const float*)d_in[1];
    const float* v = (const float*)d_in[2];
    const float* a = (const float*)d_in[3];
    float* out = (float*)d_out;

    int write_attn = ((size_t)out_size >= OUT_ELEMS + ATTN_ELEMS) ? 1 : 0;
    float* attnw = out + OUT_ELEMS;

    cudaFuncSetAttribute(attn_mma_kernel,
                         cudaFuncAttributeMaxDynamicSharedMemorySize, SMEM_BYTES);

    dim3 grid(BB * HH * (LQ / MT));  // 128
    attn_mma_kernel<<<grid, THREADS, SMEM_BYTES>>>(q, k, v, a, out, attnw, write_attn);
}